// round 2
// baseline (speedup 1.0000x reference)
#include <cuda_runtime.h>
#include <math.h>
#include <float.h>

#define NSAMP  160000
#define NF     998
#define FRAME  400
#define HOP    160
#define MAXB   128
#define NLAG   288      // lags 32..319
#define HLAG   152      // hnr lag slots: 50..201 (150 used)
#define HCHUNK 40
#define HCLEN  4000
#define TOTTILE 1026    // sum over g of (46-g), g=0..35

// ------------------------- device scratch (static, no allocs) ---------------
__device__ float g_rms[MAXB*NF];
__device__ float g_zcr[MAXB*NF];
__device__ float g_amp[MAXB*NF];
__device__ float g_f0 [MAXB*NF];
__device__ float g_val[MAXB*NF];
__device__ int   g_pos[MAXB][NSAMP];
__device__ float g_sig[MAXB][12];
// [0]e_mean [1]e_std [2]z_mean [3]z_std [4]f0_mean [5]f0_std [6]voicing
// [7]shimmer [8]nper [9]mean_period [10]mean_pdiff [11]hnr
__device__ float g_hnrp[(size_t)MAXB*HCHUNK*HLAG];

// ------------------------- K1: per-frame stats + autocorr -------------------
// 288 threads. Lag phase: work-balanced partition of 36 lag-groups (8 lags
// each) into 288 threads; each thread gets a multiple-of-8 t-range with no
// inner guards (smem zero-padded so out-of-frame products are exactly 0).
__global__ __launch_bounds__(288) void k_frames(const float* __restrict__ audio)
{
    const int f = blockIdx.x, b = blockIdx.y;
    const int tid = threadIdx.x;
    __shared__ float s[416];
    __shared__ float part[288*8];   // [thread][j]
    __shared__ float acbuf[NLAG];
    __shared__ float wred[27];
    __shared__ float tot[3];

    const float* a = audio + (size_t)b*NSAMP + (size_t)f*HOP;
    for (int i = tid; i < 416; i += 288) s[i] = (i < FRAME) ? a[i] : 0.f;
    __syncthreads();

    // sumsq / max|x| / zero-crossing sum
    float ss = 0.f, am = 0.f, zc = 0.f;
    for (int i = tid; i < FRAME; i += 288) {
        float x = s[i];
        ss += x*x;
        am = fmaxf(am, fabsf(x));
        if (i >= 1) {
            float p  = s[i-1];
            float sg = (float)((x > 0.f) - (x < 0.f));
            float sp = (float)((p > 0.f) - (p < 0.f));
            zc += fabsf(sg - sp);
        }
    }
    for (int o = 16; o; o >>= 1) {
        ss += __shfl_xor_sync(0xffffffffu, ss, o);
        zc += __shfl_xor_sync(0xffffffffu, zc, o);
        am  = fmaxf(am, __shfl_xor_sync(0xffffffffu, am, o));
    }
    int w = tid >> 5, ln = tid & 31;
    if (ln == 0) { wred[w] = ss; wred[9+w] = zc; wred[18+w] = am; }
    __syncthreads();
    if (tid == 0) {
        float S=0.f, Z=0.f, A=0.f;
        for (int q = 0; q < 9; q++) { S += wred[q]; Z += wred[9+q]; A = fmaxf(A, wred[18+q]); }
        tot[0]=S; tot[1]=Z; tot[2]=A;
    }

    // ---- balanced lag phase ----
    // group g: lags L0=32+8g .. L0+7, tiles n8(g)=46-g (each tile = 8 t-samples)
    // thread allocation: S(g) = floor(cum(g)*288/1026); thread tid in group g
    // iff S(g) <= tid < S(g+1).
    {
        int myg = 0, myq = 0, t0 = 0, t1 = 0;
        int prevS = 0, cumtile = 0;
        #pragma unroll 1
        for (int gg = 0; gg < 36; ++gg) {
            int n8 = 46 - gg;
            int nextcum = cumtile + n8;
            int nextS = (nextcum * 288) / TOTTILE;
            if (tid < nextS) {
                myg = gg;
                myq = tid - prevS;
                int nseg = nextS - prevS;
                t0 = ((myq * n8) / nseg) * 8;
                t1 = (((myq + 1) * n8) / nseg) * 8;
                break;
            }
            prevS = nextS; cumtile = nextcum;
        }
        int L0 = 32 + myg*8;
        float wreg[8], acc[8];
#pragma unroll
        for (int j = 0; j < 8; j++) { wreg[j] = s[t0 + L0 + j]; acc[j] = 0.f; }
        #pragma unroll 1
        for (int tb = t0; tb < t1; tb += 8) {
#pragma unroll
            for (int u = 0; u < 8; u++) {
                float bb = s[tb + u];
#pragma unroll
                for (int j = 0; j < 8; j++) acc[j] += bb * wreg[(u + j) & 7];
                wreg[u] = s[tb + u + L0 + 8];
            }
        }
#pragma unroll
        for (int j = 0; j < 8; j++) part[tid*8 + j] = acc[j];
    }
    __syncthreads();
    // reduce: lag slot tid -> (g = tid>>3, j = tid&7); lag = 32 + tid
    {
        int g2 = tid >> 3, j2 = tid & 7;
        int cumg  = 46*g2 - (g2*(g2-1))/2;
        int Sg  = (cumg * 288) / TOTTILE;
        int Sg1 = ((cumg + 46 - g2) * 288) / TOTTILE;
        float v = 0.f;
        for (int q = Sg; q < Sg1; q++) v += part[q*8 + j2];
        acbuf[tid] = v;
    }
    __syncthreads();

    // argmax with first-max tie rule (np.argmax)
    if (tid < 32) {
        float bv = -FLT_MAX; int bi = 0;
        for (int l = tid; l < NLAG; l += 32) {
            float v = acbuf[l];
            if (v > bv) { bv = v; bi = l; }
        }
        for (int o = 16; o; o >>= 1) {
            float ov = __shfl_down_sync(0xffffffffu, bv, o);
            int   oi = __shfl_down_sync(0xffffffffu, bi, o);
            if (ov > bv || (ov == bv && oi < bi)) { bv = ov; bi = oi; }
        }
        if (tid == 0) {
            int idx = b*NF + f;
            float S = tot[0];
            float rms = sqrtf(S / (float)FRAME);
            float zcr = tot[1] / (2.f * (float)FRAME);
            int peak = bi + 32;
            float f0 = 16000.f / (float)peak;
            float valid = (bv > 0.3f*S && f0 > 50.f && f0 < 500.f) ? 1.f : 0.f;
            g_rms[idx] = rms; g_zcr[idx] = zcr; g_amp[idx] = tot[2];
            g_f0[idx] = f0;  g_val[idx] = valid;
        }
    }
}

// ------------------------- K2: per-signal frame aggregation -----------------
__device__ __forceinline__ float blockReduce512(float v, float* sred, int tid)
{
    sred[tid] = v; __syncthreads();
    for (int st = 256; st > 0; st >>= 1) {
        if (tid < st) sred[tid] += sred[tid + st];
        __syncthreads();
    }
    float r = sred[0]; __syncthreads();
    return r;
}

__global__ __launch_bounds__(512) void k_sigstats()
{
    int b = blockIdx.x, tid = threadIdx.x;
    __shared__ float sred[512];
    __shared__ float samp[1024];
    __shared__ int   cA[1024], cB[1024];
    __shared__ float comp[1024];

    float sr=0.f, sz=0.f, sf=0.f, fc=0.f, vo=0.f;
    for (int i = tid; i < NF; i += 512) {
        float r = g_rms[b*NF+i], z = g_zcr[b*NF+i];
        float f = g_f0[b*NF+i],  v = g_val[b*NF+i];
        sr += r; sz += z; sf += f*v; fc += v;
        vo += (r > 0.01f && z < 0.3f) ? 1.f : 0.f;
    }
    float SR = blockReduce512(sr, sred, tid);
    float SZ = blockReduce512(sz, sred, tid);
    float SF = blockReduce512(sf, sred, tid);
    float FC = blockReduce512(fc, sred, tid);
    float VO = blockReduce512(vo, sred, tid);

    float e_mean = SR / (float)NF;
    float z_mean = SZ / (float)NF;
    float f0_mean = SF / fmaxf(FC, 1.f);

    float dr=0.f, dz=0.f, df=0.f;
    for (int i = tid; i < NF; i += 512) {
        float r = g_rms[b*NF+i], z = g_zcr[b*NF+i];
        float f = g_f0[b*NF+i],  v = g_val[b*NF+i];
        float a1 = r - e_mean, a2 = z - z_mean, a3 = f - f0_mean;
        dr += a1*a1; dz += a2*a2; df += a3*a3*v;
    }
    float DR = blockReduce512(dr, sred, tid);
    float DZ = blockReduce512(dz, sred, tid);
    float DF = blockReduce512(df, sred, tid);

    float e_std  = sqrtf(DR / (float)NF);
    float z_std  = sqrtf(DZ / (float)NF);
    float f0_std = (FC > 0.f) ? sqrtf(DF / fmaxf(FC, 1.f)) : 0.f;
    float f0_m   = (FC > 0.f) ? f0_mean : 0.f;

    // shimmer: stable compaction of amp>0.01 via inclusive scan
    for (int i = tid; i < 1024; i += 512) samp[i] = (i < NF) ? g_amp[b*NF+i] : 0.f;
    __syncthreads();
    for (int i = tid; i < 1024; i += 512) cA[i] = (samp[i] > 0.01f) ? 1 : 0;
    __syncthreads();
    int* src = cA; int* dst = cB;
    for (int d = 1; d < 1024; d <<= 1) {
        for (int i = tid; i < 1024; i += 512) dst[i] = src[i] + ((i >= d) ? src[i-d] : 0);
        __syncthreads();
        int* t_ = src; src = dst; dst = t_;
    }
    int ka = src[NF-1];
    for (int i = tid; i < 1024; i += 512)
        if (i < NF && samp[i] > 0.01f) comp[src[i]-1] = samp[i];
    __syncthreads();
    float sd=0.f, sa=0.f;
    for (int r = tid; r < ka; r += 512) {
        sa += comp[r];
        if (r + 1 < ka) sd += fabsf(comp[r+1] - comp[r]);
    }
    float SA = blockReduce512(sa, sred, tid);
    float SD = blockReduce512(sd, sred, tid);

    if (tid == 0) {
        float mean_amp = SA / fmaxf((float)ka, 1.f);
        float mean_ad  = SD / fmaxf((float)(ka-1), 1.f);
        float shim = 0.f;
        if (ka >= 2 && mean_amp > 0.f)
            shim = fminf(fmaxf(mean_ad / fmaxf(mean_amp, 1e-12f), 0.f), 1.f);
        g_sig[b][0]=e_mean; g_sig[b][1]=e_std; g_sig[b][2]=z_mean; g_sig[b][3]=z_std;
        g_sig[b][4]=f0_m;   g_sig[b][5]=f0_std;
        g_sig[b][6]=VO/(float)NF; g_sig[b][7]=shim;
    }
}

// ------------------------- K3: jitter (crossings) ---------------------------
__global__ __launch_bounds__(1024) void k_jitter(const float* __restrict__ audio)
{
    int b = blockIdx.x, tid = threadIdx.x;
    __shared__ float sred[1024];
    __shared__ int wcnt[32], woff[32];
    __shared__ int sbase;
    __shared__ float sthr;
    const float* a = audio + (size_t)b*NSAMP;

    float am = 0.f;
    for (int i = tid; i < NSAMP; i += 1024) am = fmaxf(am, fabsf(a[i]));
    sred[tid] = am; __syncthreads();
    for (int st = 512; st > 0; st >>= 1) {
        if (tid < st) sred[tid] = fmaxf(sred[tid], sred[tid+st]);
        __syncthreads();
    }
    if (tid == 0) { sthr = 0.3f * sred[0]; sbase = 0; }
    __syncthreads();
    float thr = sthr;
    int warp = tid >> 5, lane = tid & 31;

    for (int start = 1; start < NSAMP; start += 1024) {
        int i = start + tid;
        bool cross = false;
        if (i < NSAMP) cross = (a[i-1] < thr) && (a[i] >= thr);
        unsigned m = __ballot_sync(0xffffffffu, cross);
        if (lane == 0) wcnt[warp] = __popc(m);
        __syncthreads();
        if (tid == 0) { int acc = 0; for (int q = 0; q < 32; q++) { woff[q] = acc; acc += wcnt[q]; } }
        __syncthreads();
        int mybase = sbase;
        if (cross) g_pos[b][mybase + woff[warp] + __popc(m & ((1u << lane) - 1u))] = i;
        __syncthreads();
        if (tid == 0) sbase += woff[31] + wcnt[31];
        __syncthreads();
    }
    int k = sbase;

    float sd = 0.f;
    for (int j = tid; j + 2 < k; j += 1024) {
        int p0 = g_pos[b][j], p1 = g_pos[b][j+1], p2 = g_pos[b][j+2];
        sd += fabsf((float)(p2 - 2*p1 + p0));
    }
    sred[tid] = sd; __syncthreads();
    for (int st = 512; st > 0; st >>= 1) {
        if (tid < st) sred[tid] += sred[tid+st];
        __syncthreads();
    }
    if (tid == 0) {
        float nper = (float)(k - 1);
        float mp = 0.f;
        if (k >= 2) mp = (float)(g_pos[b][k-1] - g_pos[b][0]) / fmaxf(nper, 1.f);
        float mpd = sred[0] / fmaxf(nper - 1.f, 1.f);
        g_sig[b][8] = nper; g_sig[b][9] = mp; g_sig[b][10] = mpd;
    }
}

// ------------------------- K4: HNR autocorr partials ------------------------
// 19 lag-groups x 20 segments of exactly 200 samples (25x8): guard-free.
__global__ __launch_bounds__(384) void k_hnr(const float* __restrict__ audio)
{
    int c = blockIdx.x, b = blockIdx.y;
    int tid = threadIdx.x;
    __shared__ float s[4224];
    __shared__ float part[HLAG*20];
    const float* a = audio + (size_t)b*NSAMP;
    int base = c*HCLEN;
    for (int i = tid; i < 4224; i += 384) {
        int gi = base + i;
        s[i] = (gi < NSAMP) ? a[gi] : 0.f;
    }
    __syncthreads();
    if (tid < 380) {
        int g = tid/20, sg = tid%20;
        int L0 = 50 + g*8;
        int t0 = sg*200;
        float wreg[8], acc[8];
#pragma unroll
        for (int j = 0; j < 8; j++) { wreg[j] = s[t0 + L0 + j]; acc[j] = 0.f; }
        #pragma unroll 1
        for (int tb = t0; tb < t0 + 200; tb += 8) {
#pragma unroll
            for (int u = 0; u < 8; u++) {
                float bb = s[tb + u];
#pragma unroll
                for (int j = 0; j < 8; j++) acc[j] += bb * wreg[(u + j) & 7];
                wreg[u] = s[tb + u + L0 + 8];
            }
        }
#pragma unroll
        for (int j = 0; j < 8; j++) part[(g*8 + j)*20 + sg] = acc[j];
    }
    __syncthreads();
    if (tid < HLAG) {
        float v = 0.f;
#pragma unroll
        for (int q = 0; q < 20; q++) v += part[tid*20 + q];
        g_hnrp[((size_t)b*HCHUNK + c)*HLAG + tid] = v;
    }
}

// ------------------------- K5: HNR finalize (sort + percentile) -------------
__global__ __launch_bounds__(256) void k_hnrfin()
{
    int b = blockIdx.x, tid = threadIdx.x;
    __shared__ float v[256];
    float x = FLT_MAX;
    if (tid < 150) {
        float sacc = 0.f;
        for (int c = 0; c < HCHUNK; c++) sacc += g_hnrp[((size_t)b*HCHUNK + c)*HLAG + tid];
        x = sacc;
    }
    v[tid] = x; __syncthreads();
    for (int k = 2; k <= 256; k <<= 1) {
        for (int j = k >> 1; j > 0; j >>= 1) {
            int ixj = tid ^ j;
            if (ixj > tid) {
                bool up = ((tid & k) == 0);
                float a0 = v[tid], a1 = v[ixj];
                if ((a0 > a1) == up) { v[tid] = a1; v[ixj] = a0; }
            }
            __syncthreads();
        }
    }
    if (tid == 0) {
        float nfl = v[14] + 0.9f*(v[15] - v[14]);  // percentile 10, linear interp
        float sp  = v[149];                          // max of 150 values
        float h = 0.f;
        if (nfl > 0.f) h = fminf(fmaxf(sp / fmaxf(nfl, 1e-30f) / 100.f, 0.f), 1.f);
        g_sig[b][11] = h;
    }
}

// ------------------------- K6: finalize metrics + projection ----------------
__global__ __launch_bounds__(128) void k_final(
    const float* __restrict__ W1, const float* __restrict__ b1,
    const float* __restrict__ gamma, const float* __restrict__ beta,
    const float* __restrict__ W2, const float* __restrict__ b2,
    float* __restrict__ out, int out_size, int B)
{
    int b = blockIdx.x, tid = threadIdx.x;
    __shared__ float feats[10], met[10], hbuf[64], h2[64];
    if (tid == 0) {
        float e_mean=g_sig[b][0], e_std=g_sig[b][1], z_mean=g_sig[b][2], z_std=g_sig[b][3];
        float f0m=g_sig[b][4], f0s=g_sig[b][5], voic=g_sig[b][6], shim=g_sig[b][7];
        float nper=g_sig[b][8], mp=g_sig[b][9], mpd=g_sig[b][10], hnr=g_sig[b][11];
        float jit = 0.f;
        if (nper >= 2.f && mp > 0.f) jit = fminf(fmaxf(mpd / fmaxf(mp, 1e-12f), 0.f), 1.f);
        if (f0m < 50.f || f0m > 500.f) jit = 0.f;
        met[0]=f0m; met[1]=f0s; met[2]=e_mean; met[3]=e_std; met[4]=z_mean; met[5]=z_std;
        met[6]=jit; met[7]=shim; met[8]=hnr; met[9]=voic;
        feats[0]=f0m/500.f; feats[1]=f0s/100.f; feats[2]=e_mean; feats[3]=e_std;
        feats[4]=z_mean; feats[5]=z_std; feats[6]=jit; feats[7]=shim; feats[8]=hnr; feats[9]=voic;
    }
    __syncthreads();
    if (tid < 64) {
        float h = b1[tid];
#pragma unroll
        for (int i = 0; i < 10; i++) h += feats[i] * W1[tid*10 + i];
        hbuf[tid] = h;
    }
    __syncthreads();
    if (tid < 64) {
        float mu = 0.f;
        for (int j = 0; j < 64; j++) mu += hbuf[j];
        mu *= (1.f/64.f);
        float var = 0.f;
        for (int j = 0; j < 64; j++) { float d = hbuf[j] - mu; var += d*d; }
        var *= (1.f/64.f);
        float hn = (hbuf[tid] - mu) / sqrtf(var + 1e-5f) * gamma[tid] + beta[tid];
        h2[tid] = fmaxf(hn, 0.f);
    }
    __syncthreads();
    float o = b2[tid];
#pragma unroll 8
    for (int j = 0; j < 64; j++) o += h2[j] * W2[tid*64 + j];

    if (out_size >= B*138) {
        out[b*128 + tid] = o;
        if (tid < 10) out[B*128 + b*10 + tid] = met[tid];
    } else if (out_size >= B*128) {
        out[b*128 + tid] = o;
    } else {
        if (tid < 10) out[b*10 + tid] = met[tid];
    }
}

// ------------------------- launch -------------------------------------------
extern "C" void kernel_launch(void* const* d_in, const int* in_sizes, int n_in,
                              void* d_out, int out_size)
{
    const float* audio = (const float*)d_in[0];
    const float* W1    = (const float*)d_in[1];
    const float* b1    = (const float*)d_in[2];
    const float* gamma = (const float*)d_in[3];
    const float* beta  = (const float*)d_in[4];
    const float* W2    = (const float*)d_in[5];
    const float* b2    = (const float*)d_in[6];
    int B = in_sizes[0] / NSAMP;
    if (B > MAXB) B = MAXB;

    dim3 g1(NF, B);
    k_frames<<<g1, 288>>>(audio);
    k_sigstats<<<B, 512>>>();
    k_jitter<<<B, 1024>>>(audio);
    dim3 g4(HCHUNK, B);
    k_hnr<<<g4, 384>>>(audio);
    k_hnrfin<<<B, 256>>>();
    k_final<<<B, 128>>>(W1, b1, gamma, beta, W2, b2, (float*)d_out, out_size, B);
}

// round 3
// speedup vs baseline: 1.1001x; 1.1001x over previous
#include <cuda_runtime.h>
#include <math.h>
#include <float.h>

#define NSAMP  160000
#define NF     998
#define FRAME  400
#define HOP    160
#define MAXB   128
#define NLAG   288      // lags 32..319
#define HLAG   152      // hnr lag slots (150 used: lags 50..199)
#define HCHUNK 40
#define HCLEN  4000
#define TOT16  261      // sum over g of (23-g), g=0..17  (16-sample tiles)

// padded smem index: insert one float after every 8
#define PIDX(i) ((i) + ((i) >> 3))

// ------------------------- device scratch (static, no allocs) ---------------
__device__ float g_rms[MAXB*NF];
__device__ float g_zcr[MAXB*NF];
__device__ float g_amp[MAXB*NF];
__device__ float g_f0 [MAXB*NF];
__device__ float g_val[MAXB*NF];
__device__ int   g_pos[MAXB][NSAMP];
__device__ float g_sig[MAXB][12];
__device__ float g_hnrp[(size_t)MAXB*HCHUNK*HLAG];

// ------------------------- K1: per-frame stats + autocorr -------------------
// 288 threads. 18 lag-groups of 16 lags (L0 = 32+16g). Work-balanced thread
// partition over 16-sample tiles. Padded smem for low bank conflicts.
__global__ __launch_bounds__(288) void k_frames(const float* __restrict__ audio)
{
    const int f = blockIdx.x, b = blockIdx.y;
    const int tid = threadIdx.x;
    __shared__ float s[468];          // PIDX(415)=466
    __shared__ float part[16*289];    // [j][thread], stride 289 (odd)
    __shared__ float acbuf[NLAG];
    __shared__ float wred[27];
    __shared__ float tot[3];

    const float* a = audio + (size_t)b*NSAMP + (size_t)f*HOP;
    for (int i = tid; i < 416; i += 288) s[PIDX(i)] = (i < FRAME) ? a[i] : 0.f;
    __syncthreads();

    // sumsq / max|x| / zero-crossing sum
    float ss = 0.f, am = 0.f, zc = 0.f;
    for (int i = tid; i < FRAME; i += 288) {
        float x = s[PIDX(i)];
        ss += x*x;
        am = fmaxf(am, fabsf(x));
        if (i >= 1) {
            float p  = s[PIDX(i-1)];
            float sg = (float)((x > 0.f) - (x < 0.f));
            float sp = (float)((p > 0.f) - (p < 0.f));
            zc += fabsf(sg - sp);
        }
    }
    for (int o = 16; o; o >>= 1) {
        ss += __shfl_xor_sync(0xffffffffu, ss, o);
        zc += __shfl_xor_sync(0xffffffffu, zc, o);
        am  = fmaxf(am, __shfl_xor_sync(0xffffffffu, am, o));
    }
    int w = tid >> 5, ln = tid & 31;
    if (ln == 0) { wred[w] = ss; wred[9+w] = zc; wred[18+w] = am; }
    __syncthreads();
    if (tid == 0) {
        float S=0.f, Z=0.f, A=0.f;
        for (int q = 0; q < 9; q++) { S += wred[q]; Z += wred[9+q]; A = fmaxf(A, wred[18+q]); }
        tot[0]=S; tot[1]=Z; tot[2]=A;
    }

    // ---- balanced lag phase: group g has n16(g)=23-g tiles of 16 samples ----
    {
        int myg = 0, myq = 0, t0 = 0, t1 = 0;
        int prevS = 0, cumtile = 0;
        #pragma unroll 1
        for (int gg = 0; gg < 18; ++gg) {
            int n16 = 23 - gg;
            int nextcum = cumtile + n16;
            int nextS = (nextcum * 288) / TOT16;
            if (tid < nextS) {
                myg = gg;
                myq = tid - prevS;
                int nseg = nextS - prevS;
                t0 = ((myq * n16) / nseg) * 16;
                t1 = (((myq + 1) * n16) / nseg) * 16;
                break;
            }
            prevS = nextS; cumtile = nextcum;
        }
        int L0 = 32 + myg*16;
        float wreg[16], acc[16];
        int pb0 = PIDX(t0 + L0);
#pragma unroll
        for (int j = 0; j < 16; j++) { wreg[j] = s[pb0 + j + (j>>3)]; acc[j] = 0.f; }
        #pragma unroll 1
        for (int tb = t0; tb < t1; tb += 16) {
            int pB = PIDX(tb);
            int pW = PIDX(tb + L0 + 16);
#pragma unroll
            for (int u = 0; u < 16; u++) {
                float bb = s[pB + u + (u>>3)];
#pragma unroll
                for (int j = 0; j < 16; j++) acc[j] += bb * wreg[(u + j) & 15];
                wreg[u] = s[pW + u + (u>>3)];
            }
        }
#pragma unroll
        for (int j = 0; j < 16; j++) part[j*289 + tid] = acc[j];
    }
    __syncthreads();
    // reduce: lag slot tid -> (g = tid>>4, j = tid&15); lag = 32 + tid
    {
        int g2 = tid >> 4, j2 = tid & 15;
        int cumg = 23*g2 - (g2*(g2-1))/2;     // sum of (23-k), k<g2
        int Sg  = (cumg * 288) / TOT16;
        int Sg1 = ((cumg + 23 - g2) * 288) / TOT16;
        float v = 0.f;
        for (int q = Sg; q < Sg1; q++) v += part[j2*289 + q];
        acbuf[tid] = v;
    }
    __syncthreads();

    // argmax with first-max tie rule (np.argmax)
    if (tid < 32) {
        float bv = -FLT_MAX; int bi = 0;
        for (int l = tid; l < NLAG; l += 32) {
            float v = acbuf[l];
            if (v > bv) { bv = v; bi = l; }
        }
        for (int o = 16; o; o >>= 1) {
            float ov = __shfl_down_sync(0xffffffffu, bv, o);
            int   oi = __shfl_down_sync(0xffffffffu, bi, o);
            if (ov > bv || (ov == bv && oi < bi)) { bv = ov; bi = oi; }
        }
        if (tid == 0) {
            int idx = b*NF + f;
            float S = tot[0];
            float rms = sqrtf(S / (float)FRAME);
            float zcr = tot[1] / (2.f * (float)FRAME);
            int peak = bi + 32;
            float f0 = 16000.f / (float)peak;
            float valid = (bv > 0.3f*S && f0 > 50.f && f0 < 500.f) ? 1.f : 0.f;
            g_rms[idx] = rms; g_zcr[idx] = zcr; g_amp[idx] = tot[2];
            g_f0[idx] = f0;  g_val[idx] = valid;
        }
    }
}

// ------------------------- K2: per-signal frame aggregation -----------------
__device__ __forceinline__ float blockReduce512(float v, float* sred, int tid)
{
    sred[tid] = v; __syncthreads();
    for (int st = 256; st > 0; st >>= 1) {
        if (tid < st) sred[tid] += sred[tid + st];
        __syncthreads();
    }
    float r = sred[0]; __syncthreads();
    return r;
}

__global__ __launch_bounds__(512) void k_sigstats()
{
    int b = blockIdx.x, tid = threadIdx.x;
    __shared__ float sred[512];
    __shared__ float samp[1024];
    __shared__ int   cA[1024], cB[1024];
    __shared__ float comp[1024];

    float sr=0.f, sz=0.f, sf=0.f, fc=0.f, vo=0.f;
    for (int i = tid; i < NF; i += 512) {
        float r = g_rms[b*NF+i], z = g_zcr[b*NF+i];
        float f = g_f0[b*NF+i],  v = g_val[b*NF+i];
        sr += r; sz += z; sf += f*v; fc += v;
        vo += (r > 0.01f && z < 0.3f) ? 1.f : 0.f;
    }
    float SR = blockReduce512(sr, sred, tid);
    float SZ = blockReduce512(sz, sred, tid);
    float SF = blockReduce512(sf, sred, tid);
    float FC = blockReduce512(fc, sred, tid);
    float VO = blockReduce512(vo, sred, tid);

    float e_mean = SR / (float)NF;
    float z_mean = SZ / (float)NF;
    float f0_mean = SF / fmaxf(FC, 1.f);

    float dr=0.f, dz=0.f, df=0.f;
    for (int i = tid; i < NF; i += 512) {
        float r = g_rms[b*NF+i], z = g_zcr[b*NF+i];
        float f = g_f0[b*NF+i],  v = g_val[b*NF+i];
        float a1 = r - e_mean, a2 = z - z_mean, a3 = f - f0_mean;
        dr += a1*a1; dz += a2*a2; df += a3*a3*v;
    }
    float DR = blockReduce512(dr, sred, tid);
    float DZ = blockReduce512(dz, sred, tid);
    float DF = blockReduce512(df, sred, tid);

    float e_std  = sqrtf(DR / (float)NF);
    float z_std  = sqrtf(DZ / (float)NF);
    float f0_std = (FC > 0.f) ? sqrtf(DF / fmaxf(FC, 1.f)) : 0.f;
    float f0_m   = (FC > 0.f) ? f0_mean : 0.f;

    for (int i = tid; i < 1024; i += 512) samp[i] = (i < NF) ? g_amp[b*NF+i] : 0.f;
    __syncthreads();
    for (int i = tid; i < 1024; i += 512) cA[i] = (samp[i] > 0.01f) ? 1 : 0;
    __syncthreads();
    int* src = cA; int* dst = cB;
    for (int d = 1; d < 1024; d <<= 1) {
        for (int i = tid; i < 1024; i += 512) dst[i] = src[i] + ((i >= d) ? src[i-d] : 0);
        __syncthreads();
        int* t_ = src; src = dst; dst = t_;
    }
    int ka = src[NF-1];
    for (int i = tid; i < 1024; i += 512)
        if (i < NF && samp[i] > 0.01f) comp[src[i]-1] = samp[i];
    __syncthreads();
    float sd=0.f, sa=0.f;
    for (int r = tid; r < ka; r += 512) {
        sa += comp[r];
        if (r + 1 < ka) sd += fabsf(comp[r+1] - comp[r]);
    }
    float SA = blockReduce512(sa, sred, tid);
    float SD = blockReduce512(sd, sred, tid);

    if (tid == 0) {
        float mean_amp = SA / fmaxf((float)ka, 1.f);
        float mean_ad  = SD / fmaxf((float)(ka-1), 1.f);
        float shim = 0.f;
        if (ka >= 2 && mean_amp > 0.f)
            shim = fminf(fmaxf(mean_ad / fmaxf(mean_amp, 1e-12f), 0.f), 1.f);
        g_sig[b][0]=e_mean; g_sig[b][1]=e_std; g_sig[b][2]=z_mean; g_sig[b][3]=z_std;
        g_sig[b][4]=f0_m;   g_sig[b][5]=f0_std;
        g_sig[b][6]=VO/(float)NF; g_sig[b][7]=shim;
    }
}

// ------------------------- K3: jitter (crossings) ---------------------------
__global__ __launch_bounds__(1024) void k_jitter(const float* __restrict__ audio)
{
    int b = blockIdx.x, tid = threadIdx.x;
    __shared__ float sred[1024];
    __shared__ int wcnt[32], woff[32];
    __shared__ int sbase;
    __shared__ float sthr;
    const float* a = audio + (size_t)b*NSAMP;

    float am = 0.f;
    for (int i = tid; i < NSAMP; i += 1024) am = fmaxf(am, fabsf(a[i]));
    sred[tid] = am; __syncthreads();
    for (int st = 512; st > 0; st >>= 1) {
        if (tid < st) sred[tid] = fmaxf(sred[tid], sred[tid+st]);
        __syncthreads();
    }
    if (tid == 0) { sthr = 0.3f * sred[0]; sbase = 0; }
    __syncthreads();
    float thr = sthr;
    int warp = tid >> 5, lane = tid & 31;

    for (int start = 1; start < NSAMP; start += 1024) {
        int i = start + tid;
        bool cross = false;
        if (i < NSAMP) cross = (a[i-1] < thr) && (a[i] >= thr);
        unsigned m = __ballot_sync(0xffffffffu, cross);
        if (lane == 0) wcnt[warp] = __popc(m);
        __syncthreads();
        if (tid == 0) { int acc = 0; for (int q = 0; q < 32; q++) { woff[q] = acc; acc += wcnt[q]; } }
        __syncthreads();
        int mybase = sbase;
        if (cross) g_pos[b][mybase + woff[warp] + __popc(m & ((1u << lane) - 1u))] = i;
        __syncthreads();
        if (tid == 0) sbase += woff[31] + wcnt[31];
        __syncthreads();
    }
    int k = sbase;

    float sd = 0.f;
    for (int j = tid; j + 2 < k; j += 1024) {
        int p0 = g_pos[b][j], p1 = g_pos[b][j+1], p2 = g_pos[b][j+2];
        sd += fabsf((float)(p2 - 2*p1 + p0));
    }
    sred[tid] = sd; __syncthreads();
    for (int st = 512; st > 0; st >>= 1) {
        if (tid < st) sred[tid] += sred[tid+st];
        __syncthreads();
    }
    if (tid == 0) {
        float nper = (float)(k - 1);
        float mp = 0.f;
        if (k >= 2) mp = (float)(g_pos[b][k-1] - g_pos[b][0]) / fmaxf(nper, 1.f);
        float mpd = sred[0] / fmaxf(nper - 1.f, 1.f);
        g_sig[b][8] = nper; g_sig[b][9] = mp; g_sig[b][10] = mpd;
    }
}

// ------------------------- K4: HNR autocorr partials ------------------------
// 10 lag-groups of 16 lags (L0 = 48+16g, lags 48..207, keep 50..199).
// 32 segments per group; padded smem; 320 threads (warps pure-g).
__global__ __launch_bounds__(320) void k_hnr(const float* __restrict__ audio)
{
    int c = blockIdx.x, b = blockIdx.y;
    int tid = threadIdx.x;
    __shared__ float s[4752];         // PIDX(4223)=4750
    __shared__ float part[16*321];
    const float* a = audio + (size_t)b*NSAMP;
    int base = c*HCLEN;
    for (int i = tid; i < 4224; i += 320) {
        int gi = base + i;
        s[PIDX(i)] = (gi < NSAMP) ? a[gi] : 0.f;
    }
    __syncthreads();
    {
        int g = tid >> 5, sg = tid & 31;
        int L0 = 48 + g*16;
        int t0 = ((sg*250) >> 5) * 16;
        int t1 = (((sg+1)*250) >> 5) * 16;
        float wreg[16], acc[16];
        int pb0 = PIDX(t0 + L0);
#pragma unroll
        for (int j = 0; j < 16; j++) { wreg[j] = s[pb0 + j + (j>>3)]; acc[j] = 0.f; }
        #pragma unroll 1
        for (int tb = t0; tb < t1; tb += 16) {
            int pB = PIDX(tb);
            int pW = PIDX(tb + L0 + 16);
#pragma unroll
            for (int u = 0; u < 16; u++) {
                float bb = s[pB + u + (u>>3)];
#pragma unroll
                for (int j = 0; j < 16; j++) acc[j] += bb * wreg[(u + j) & 15];
                wreg[u] = s[pW + u + (u>>3)];
            }
        }
#pragma unroll
        for (int j = 0; j < 16; j++) part[j*321 + tid] = acc[j];
    }
    __syncthreads();
    if (tid < 160) {
        int g2 = tid >> 4, j2 = tid & 15;
        int lag = 48 + g2*16 + j2;
        if (lag >= 50 && lag <= 199) {
            float v = 0.f;
#pragma unroll
            for (int q = 0; q < 32; q++) v += part[j2*321 + g2*32 + q];
            g_hnrp[((size_t)b*HCHUNK + c)*HLAG + (lag - 50)] = v;
        }
    }
}

// ------------------------- K5: HNR finalize (sort + percentile) -------------
__global__ __launch_bounds__(256) void k_hnrfin()
{
    int b = blockIdx.x, tid = threadIdx.x;
    __shared__ float v[256];
    float x = FLT_MAX;
    if (tid < 150) {
        float sacc = 0.f;
        for (int c = 0; c < HCHUNK; c++) sacc += g_hnrp[((size_t)b*HCHUNK + c)*HLAG + tid];
        x = sacc;
    }
    v[tid] = x; __syncthreads();
    for (int k = 2; k <= 256; k <<= 1) {
        for (int j = k >> 1; j > 0; j >>= 1) {
            int ixj = tid ^ j;
            if (ixj > tid) {
                bool up = ((tid & k) == 0);
                float a0 = v[tid], a1 = v[ixj];
                if ((a0 > a1) == up) { v[tid] = a1; v[ixj] = a0; }
            }
            __syncthreads();
        }
    }
    if (tid == 0) {
        float nfl = v[14] + 0.9f*(v[15] - v[14]);  // percentile 10, linear interp
        float sp  = v[149];                          // max of 150 values
        float h = 0.f;
        if (nfl > 0.f) h = fminf(fmaxf(sp / fmaxf(nfl, 1e-30f) / 100.f, 0.f), 1.f);
        g_sig[b][11] = h;
    }
}

// ------------------------- K6: finalize metrics + projection ----------------
__global__ __launch_bounds__(128) void k_final(
    const float* __restrict__ W1, const float* __restrict__ b1,
    const float* __restrict__ gamma, const float* __restrict__ beta,
    const float* __restrict__ W2, const float* __restrict__ b2,
    float* __restrict__ out, int out_size, int B)
{
    int b = blockIdx.x, tid = threadIdx.x;
    __shared__ float feats[10], met[10], hbuf[64], h2[64];
    if (tid == 0) {
        float e_mean=g_sig[b][0], e_std=g_sig[b][1], z_mean=g_sig[b][2], z_std=g_sig[b][3];
        float f0m=g_sig[b][4], f0s=g_sig[b][5], voic=g_sig[b][6], shim=g_sig[b][7];
        float nper=g_sig[b][8], mp=g_sig[b][9], mpd=g_sig[b][10], hnr=g_sig[b][11];
        float jit = 0.f;
        if (nper >= 2.f && mp > 0.f) jit = fminf(fmaxf(mpd / fmaxf(mp, 1e-12f), 0.f), 1.f);
        if (f0m < 50.f || f0m > 500.f) jit = 0.f;
        met[0]=f0m; met[1]=f0s; met[2]=e_mean; met[3]=e_std; met[4]=z_mean; met[5]=z_std;
        met[6]=jit; met[7]=shim; met[8]=hnr; met[9]=voic;
        feats[0]=f0m/500.f; feats[1]=f0s/100.f; feats[2]=e_mean; feats[3]=e_std;
        feats[4]=z_mean; feats[5]=z_std; feats[6]=jit; feats[7]=shim; feats[8]=hnr; feats[9]=voic;
    }
    __syncthreads();
    if (tid < 64) {
        float h = b1[tid];
#pragma unroll
        for (int i = 0; i < 10; i++) h += feats[i] * W1[tid*10 + i];
        hbuf[tid] = h;
    }
    __syncthreads();
    if (tid < 64) {
        float mu = 0.f;
        for (int j = 0; j < 64; j++) mu += hbuf[j];
        mu *= (1.f/64.f);
        float var = 0.f;
        for (int j = 0; j < 64; j++) { float d = hbuf[j] - mu; var += d*d; }
        var *= (1.f/64.f);
        float hn = (hbuf[tid] - mu) / sqrtf(var + 1e-5f) * gamma[tid] + beta[tid];
        h2[tid] = fmaxf(hn, 0.f);
    }
    __syncthreads();
    float o = b2[tid];
#pragma unroll 8
    for (int j = 0; j < 64; j++) o += h2[j] * W2[tid*64 + j];

    if (out_size >= B*138) {
        out[b*128 + tid] = o;
        if (tid < 10) out[B*128 + b*10 + tid] = met[tid];
    } else if (out_size >= B*128) {
        out[b*128 + tid] = o;
    } else {
        if (tid < 10) out[b*10 + tid] = met[tid];
    }
}

// ------------------------- launch -------------------------------------------
extern "C" void kernel_launch(void* const* d_in, const int* in_sizes, int n_in,
                              void* d_out, int out_size)
{
    const float* audio = (const float*)d_in[0];
    const float* W1    = (const float*)d_in[1];
    const float* b1    = (const float*)d_in[2];
    const float* gamma = (const float*)d_in[3];
    const float* beta  = (const float*)d_in[4];
    const float* W2    = (const float*)d_in[5];
    const float* b2    = (const float*)d_in[6];
    int B = in_sizes[0] / NSAMP;
    if (B > MAXB) B = MAXB;

    dim3 g1(NF, B);
    k_frames<<<g1, 288>>>(audio);
    k_sigstats<<<B, 512>>>();
    k_jitter<<<B, 1024>>>(audio);
    dim3 g4(HCHUNK, B);
    k_hnr<<<g4, 320>>>(audio);
    k_hnrfin<<<B, 256>>>();
    k_final<<<B, 128>>>(W1, b1, gamma, beta, W2, b2, (float*)d_out, out_size, B);
}